// round 2
// baseline (speedup 1.0000x reference)
#include <cuda_runtime.h>
#include <cuda_bf16.h>
#include <cstdint>

// ============================================================================
// CESLayer: out[b,o] = cos( x@angle^T + bias ) * exp( x@log|w|^T )
// B=262144, I=O=128.  mma.sync bf16 (base sm_103 PTX target — tcgen05 is
// rejected by this toolchain) with hi/lo split: xh*Wh + xl*Wh + xh*Wl.
// Persistent kernel: W resident in smem, 148 CTAs x 256 threads.
// ============================================================================

#define N_TILES   2048
#define LDS_STRIDE 136            // bf16 elems per smem row (128 + 8 pad) -> ldmatrix conflict-free

// smem byte offsets
#define OFF_XH   0u
#define OFF_XL   34816u           // 128*136*2
#define OFF_W    69632u           // 4 mats * 34816: [logH, logL, angH, angL]
#define OFF_BIAS 208896u
#define SMEM_BYTES 209664u

// Pre-split weights (bf16 hi/lo of log|w| and angle), [mat][o][i], i contiguous.
__device__ __align__(16) __nv_bfloat16 g_W[4 * 16384];

// ---------------------------------------------------------------------------
__device__ __forceinline__ uint32_t smem_u32(const void* p) {
    uint32_t a;
    asm("{ .reg .u64 t; cvta.to.shared.u64 t, %1; cvt.u32.u64 %0, t; }"
        : "=r"(a) : "l"(p));
    return a;
}

__device__ __forceinline__ uint32_t b2u(__nv_bfloat162 v) {
    return *reinterpret_cast<uint32_t*>(&v);
}

__device__ __forceinline__ void ldsm_x4(uint32_t r[4], uint32_t addr) {
    asm volatile("ldmatrix.sync.aligned.m8n8.x4.shared.b16 {%0,%1,%2,%3}, [%4];"
                 : "=r"(r[0]), "=r"(r[1]), "=r"(r[2]), "=r"(r[3]) : "r"(addr));
}

__device__ __forceinline__ void mma16816(float c[4], const uint32_t a[4],
                                         uint32_t b0, uint32_t b1) {
    asm volatile(
        "mma.sync.aligned.m16n8k16.row.col.f32.bf16.bf16.f32 "
        "{%0,%1,%2,%3}, {%4,%5,%6,%7}, {%8,%9}, {%0,%1,%2,%3};"
        : "+f"(c[0]), "+f"(c[1]), "+f"(c[2]), "+f"(c[3])
        : "r"(a[0]), "r"(a[1]), "r"(a[2]), "r"(a[3]), "r"(b0), "r"(b1));
}

// ---------------------------------------------------------------------------
// Prep: w_real/w_imag -> log|w|, angle; split each into bf16 hi + lo.
// ---------------------------------------------------------------------------
__global__ void ces_prep(const float* __restrict__ wr, const float* __restrict__ wi) {
    int idx = blockIdx.x * blockDim.x + threadIdx.x;
    if (idx >= 16384) return;
    float a = wr[idx], b = wi[idx];
    float la = 0.5f * logf(fmaf(a, a, b * b));
    float an = atan2f(b, a);
    __nv_bfloat16 lah = __float2bfloat16(la);
    __nv_bfloat16 lal = __float2bfloat16(la - __bfloat162float(lah));
    __nv_bfloat16 anh = __float2bfloat16(an);
    __nv_bfloat16 anl = __float2bfloat16(an - __bfloat162float(anh));
    g_W[0 * 16384 + idx] = lah;
    g_W[1 * 16384 + idx] = lal;
    g_W[2 * 16384 + idx] = anh;
    g_W[3 * 16384 + idx] = anl;
}

// ---------------------------------------------------------------------------
// Main persistent kernel. 8 warps: wm = wid&3 (32 rows), wn = wid>>2 (64 cols).
// ---------------------------------------------------------------------------
__global__ void __launch_bounds__(256, 1)
ces_main(const float* __restrict__ x, const float* __restrict__ bias,
         float* __restrict__ out) {
    extern __shared__ char smem[];
    const uint32_t sb = smem_u32(smem);
    const int tid  = threadIdx.x;
    const int lane = tid & 31;
    const int wid  = tid >> 5;
    const int wm   = wid & 3;
    const int wn   = wid >> 2;

    // ---- copy W (4 x 128 x 128 bf16) into padded smem, once ----
    for (int r = tid; r < 512; r += 256) {
        const uint4* src = (const uint4*)(g_W + r * 128);
        uint4* dst = (uint4*)(smem + OFF_W + ((uint32_t)(r >> 7) * 17408u +
                                              (uint32_t)(r & 127) * LDS_STRIDE) * 2u);
        #pragma unroll
        for (int j = 0; j < 16; ++j) dst[j] = src[j];
    }
    if (tid < 128) ((float*)(smem + OFF_BIAS))[tid] = bias[tid];
    __syncthreads();

    // per-thread bias pairs (tile-invariant)
    float bs0[8], bs1[8];
    {
        const float* sbias = (const float*)(smem + OFF_BIAS);
        #pragma unroll
        for (int nt = 0; nt < 8; ++nt) {
            int c = wn * 64 + nt * 8 + 2 * (lane & 3);
            bs0[nt] = sbias[c];
            bs1[nt] = sbias[c + 1];
        }
    }

    // ldmatrix per-thread byte offsets
    const uint32_t aoff = ((uint32_t)(wm * 32 + (lane & 15)) * LDS_STRIDE +
                           (uint32_t)((lane >> 4) * 8)) * 2u;
    const uint32_t boff = ((uint32_t)(wn * 64 + ((lane & 7) | ((lane & 16) >> 1))) * LDS_STRIDE +
                           (uint32_t)(lane & 8)) * 2u;

    const int xrow0 = wid;            // rows wid + 8*j
    const int xcol  = lane * 4;       // 4 floats

    for (int tile = blockIdx.x; tile < N_TILES; tile += gridDim.x) {
        __syncthreads();  // previous tile's ldmatrix reads done before X rewrite

        // ---- load x (coalesced), split hi/lo, STS ----
        #pragma unroll
        for (int jb = 0; jb < 2; ++jb) {
            float4 v[8];
            #pragma unroll
            for (int j = 0; j < 8; ++j) {
                size_t row = (size_t)tile * 128 + xrow0 + 8 * (jb * 8 + j);
                v[j] = __ldg((const float4*)(x + row * 128 + xcol));
            }
            #pragma unroll
            for (int j = 0; j < 8; ++j) {
                int row = xrow0 + 8 * (jb * 8 + j);
                __nv_bfloat162 h0 = __float22bfloat162_rn(make_float2(v[j].x, v[j].y));
                __nv_bfloat162 h1 = __float22bfloat162_rn(make_float2(v[j].z, v[j].w));
                __nv_bfloat162 L0 = __float22bfloat162_rn(make_float2(
                    v[j].x - __bfloat162float(h0.x), v[j].y - __bfloat162float(h0.y)));
                __nv_bfloat162 L1 = __float22bfloat162_rn(make_float2(
                    v[j].z - __bfloat162float(h1.x), v[j].w - __bfloat162float(h1.y)));
                uint32_t off = ((uint32_t)row * LDS_STRIDE + (uint32_t)xcol) * 2u;
                asm volatile("st.shared.v2.b32 [%0], {%1,%2};"
                             :: "r"(sb + OFF_XH + off), "r"(b2u(h0)), "r"(b2u(h1)) : "memory");
                asm volatile("st.shared.v2.b32 [%0], {%1,%2};"
                             :: "r"(sb + OFF_XL + off), "r"(b2u(L0)), "r"(b2u(L1)) : "memory");
            }
        }
        __syncthreads();

        // ---- accumulators: [mat(log/ang)][mtile][ntile][4] ----
        float acc[2][2][8][4];
        #pragma unroll
        for (int m = 0; m < 2; ++m)
            #pragma unroll
            for (int i = 0; i < 2; ++i)
                #pragma unroll
                for (int n = 0; n < 8; ++n)
                    #pragma unroll
                    for (int q = 0; q < 4; ++q) acc[m][i][n][q] = 0.f;

        // ---- 3 split passes x 2 matrices, K=128 in 8 steps ----
        #pragma unroll
        for (int pass = 0; pass < 3; ++pass) {
            const uint32_t abase = sb + (pass == 1 ? OFF_XL : OFF_XH) + aoff;
            const uint32_t hsel  = (pass == 2) ? 1u : 0u;
            #pragma unroll
            for (int k = 0; k < 8; ++k) {
                const uint32_t kb = (uint32_t)k * 32u;   // 16 bf16 * 2B
                uint32_t a0[4], a1[4];
                ldsm_x4(a0, abase + kb);
                ldsm_x4(a1, abase + 16u * LDS_STRIDE * 2u + kb);
                #pragma unroll
                for (int m = 0; m < 2; ++m) {
                    const uint32_t wb = sb + OFF_W + (uint32_t)(m * 2 + hsel) * 34816u + boff + kb;
                    #pragma unroll
                    for (int np = 0; np < 4; ++np) {
                        uint32_t b[4];
                        ldsm_x4(b, wb + (uint32_t)np * (16u * LDS_STRIDE * 2u));
                        mma16816(acc[m][0][np * 2],     a0, b[0], b[1]);
                        mma16816(acc[m][1][np * 2],     a1, b[0], b[1]);
                        mma16816(acc[m][0][np * 2 + 1], a0, b[2], b[3]);
                        mma16816(acc[m][1][np * 2 + 1], a1, b[2], b[3]);
                    }
                }
            }
        }

        // ---- epilogue: out = cos(ang + bias) * exp(log) ----
        #pragma unroll
        for (int mt = 0; mt < 2; ++mt) {
            size_t r0 = (size_t)tile * 128 + wm * 32 + mt * 16 + (lane >> 2);
            float* p0 = out + r0 * 128 + wn * 64 + 2 * (lane & 3);
            #pragma unroll
            for (int nt = 0; nt < 8; ++nt) {
                const float* al = acc[1][mt][nt];
                const float* lg = acc[0][mt][nt];
                float2 o0, o1;
                o0.x = __cosf(al[0] + bs0[nt]) * __expf(lg[0]);
                o0.y = __cosf(al[1] + bs1[nt]) * __expf(lg[1]);
                o1.x = __cosf(al[2] + bs0[nt]) * __expf(lg[2]);
                o1.y = __cosf(al[3] + bs1[nt]) * __expf(lg[3]);
                *(float2*)(p0 + nt * 8) = o0;
                *(float2*)(p0 + nt * 8 + 8 * 128) = o1;
            }
        }
    }
}

// ---------------------------------------------------------------------------
extern "C" void kernel_launch(void* const* d_in, const int* in_sizes, int n_in,
                              void* d_out, int out_size) {
    const float* x    = (const float*)d_in[0];
    const float* wr   = (const float*)d_in[1];
    const float* wi   = (const float*)d_in[2];
    const float* bias = (const float*)d_in[3];
    float* out = (float*)d_out;
    (void)in_sizes; (void)n_in; (void)out_size;

    cudaFuncSetAttribute(ces_main, cudaFuncAttributeMaxDynamicSharedMemorySize,
                         (int)SMEM_BYTES);

    ces_prep<<<64, 256>>>(wr, wi);
    ces_main<<<148, 256, SMEM_BYTES>>>(x, bias, out);
}

// round 3
// speedup vs baseline: 1.2527x; 1.2527x over previous
#include <cuda_runtime.h>
#include <cuda_bf16.h>
#include <cstdint>

// ============================================================================
// CESLayer: out[b,o] = cos( x@angle^T + bias ) * exp( x@log|w|^T )
// B=262144, I=O=128.  mma.sync bf16 (base sm_103 PTX target) with hi/lo
// split: xh*Wh + xl*Wh + xh*Wl.  Persistent kernel, W resident in smem.
// R3: fused k-loop (each frag loaded once/k), A-frag double buffer,
//     RAW-spaced HMMA ordering.
// ============================================================================

#define N_TILES   2048
#define LDS_STRIDE 136            // bf16 elems per smem row (128+8 pad)

// smem byte offsets
#define OFF_XH   0u
#define OFF_XL   34816u           // 128*136*2
#define OFF_W    69632u           // 4 mats * 34816: [logH, logL, angH, angL]
#define OFF_BIAS 208896u
#define SMEM_BYTES 209664u

__device__ __align__(16) __nv_bfloat16 g_W[4 * 16384];

// ---------------------------------------------------------------------------
__device__ __forceinline__ uint32_t smem_u32(const void* p) {
    uint32_t a;
    asm("{ .reg .u64 t; cvta.to.shared.u64 t, %1; cvt.u32.u64 %0, t; }"
        : "=r"(a) : "l"(p));
    return a;
}

__device__ __forceinline__ uint32_t b2u(__nv_bfloat162 v) {
    return *reinterpret_cast<uint32_t*>(&v);
}

__device__ __forceinline__ void ldsm_x4(uint32_t r[4], uint32_t addr) {
    asm volatile("ldmatrix.sync.aligned.m8n8.x4.shared.b16 {%0,%1,%2,%3}, [%4];"
                 : "=r"(r[0]), "=r"(r[1]), "=r"(r[2]), "=r"(r[3]) : "r"(addr));
}

__device__ __forceinline__ void mma16816(float c[4], const uint32_t a[4],
                                         uint32_t b0, uint32_t b1) {
    asm volatile(
        "mma.sync.aligned.m16n8k16.row.col.f32.bf16.bf16.f32 "
        "{%0,%1,%2,%3}, {%4,%5,%6,%7}, {%8,%9}, {%0,%1,%2,%3};"
        : "+f"(c[0]), "+f"(c[1]), "+f"(c[2]), "+f"(c[3])
        : "r"(a[0]), "r"(a[1]), "r"(a[2]), "r"(a[3]), "r"(b0), "r"(b1));
}

// ---------------------------------------------------------------------------
__global__ void ces_prep(const float* __restrict__ wr, const float* __restrict__ wi) {
    int idx = blockIdx.x * blockDim.x + threadIdx.x;
    if (idx >= 16384) return;
    float a = wr[idx], b = wi[idx];
    float la = 0.5f * logf(fmaf(a, a, b * b));
    float an = atan2f(b, a);
    __nv_bfloat16 lah = __float2bfloat16(la);
    __nv_bfloat16 lal = __float2bfloat16(la - __bfloat162float(lah));
    __nv_bfloat16 anh = __float2bfloat16(an);
    __nv_bfloat16 anl = __float2bfloat16(an - __bfloat162float(anh));
    g_W[0 * 16384 + idx] = lah;
    g_W[1 * 16384 + idx] = lal;
    g_W[2 * 16384 + idx] = anh;
    g_W[3 * 16384 + idx] = anl;
}

// ---------------------------------------------------------------------------
// 8 warps: wm = wid&3 (32 rows), wn = wid>>2 (64 cols). Warp tile 32x64.
// ---------------------------------------------------------------------------
__global__ void __launch_bounds__(256, 1)
ces_main(const float* __restrict__ x, const float* __restrict__ bias,
         float* __restrict__ out) {
    extern __shared__ char smem[];
    const uint32_t sb = smem_u32(smem);
    const int tid  = threadIdx.x;
    const int lane = tid & 31;
    const int wid  = tid >> 5;
    const int wm   = wid & 3;
    const int wn   = wid >> 2;

    // ---- copy W into padded smem, once ----
    for (int r = tid; r < 512; r += 256) {
        const uint4* src = (const uint4*)(g_W + r * 128);
        uint4* dst = (uint4*)(smem + OFF_W + ((uint32_t)(r >> 7) * 17408u +
                                              (uint32_t)(r & 127) * LDS_STRIDE) * 2u);
        #pragma unroll
        for (int j = 0; j < 16; ++j) dst[j] = src[j];
    }
    if (tid < 128) ((float*)(smem + OFF_BIAS))[tid] = bias[tid];
    __syncthreads();

    // per-thread bias pairs (tile-invariant)
    float bs0[8], bs1[8];
    {
        const float* sbias = (const float*)(smem + OFF_BIAS);
        #pragma unroll
        for (int nt = 0; nt < 8; ++nt) {
            int c = wn * 64 + nt * 8 + 2 * (lane & 3);
            bs0[nt] = sbias[c];
            bs1[nt] = sbias[c + 1];
        }
    }

    // ldmatrix per-thread byte offsets
    const uint32_t aoff = ((uint32_t)(wm * 32 + (lane & 15)) * LDS_STRIDE +
                           (uint32_t)((lane >> 4) * 8)) * 2u;
    const uint32_t boff = ((uint32_t)(wn * 64 + ((lane & 7) | ((lane & 16) >> 1))) * LDS_STRIDE +
                           (uint32_t)(lane & 8)) * 2u;

    const uint32_t abase_h = sb + OFF_XH + aoff;
    const uint32_t abase_l = sb + OFF_XL + aoff;
    const uint32_t MI_STEP = 16u * LDS_STRIDE * 2u;

    const int xrow0 = wid;            // rows wid + 8*j
    const int xcol  = lane * 4;

    for (int tile = blockIdx.x; tile < N_TILES; tile += gridDim.x) {
        __syncthreads();  // previous tile's ldmatrix reads done before X rewrite

        // ---- load x (coalesced), split hi/lo, STS ----
        #pragma unroll
        for (int jb = 0; jb < 2; ++jb) {
            float4 v[8];
            #pragma unroll
            for (int j = 0; j < 8; ++j) {
                size_t row = (size_t)tile * 128 + xrow0 + 8 * (jb * 8 + j);
                v[j] = __ldg((const float4*)(x + row * 128 + xcol));
            }
            #pragma unroll
            for (int j = 0; j < 8; ++j) {
                int row = xrow0 + 8 * (jb * 8 + j);
                __nv_bfloat162 h0 = __float22bfloat162_rn(make_float2(v[j].x, v[j].y));
                __nv_bfloat162 h1 = __float22bfloat162_rn(make_float2(v[j].z, v[j].w));
                __nv_bfloat162 L0 = __float22bfloat162_rn(make_float2(
                    v[j].x - __bfloat162float(h0.x), v[j].y - __bfloat162float(h0.y)));
                __nv_bfloat162 L1 = __float22bfloat162_rn(make_float2(
                    v[j].z - __bfloat162float(h1.x), v[j].w - __bfloat162float(h1.y)));
                uint32_t off = ((uint32_t)row * LDS_STRIDE + (uint32_t)xcol) * 2u;
                asm volatile("st.shared.v2.b32 [%0], {%1,%2};"
                             :: "r"(sb + OFF_XH + off), "r"(b2u(h0)), "r"(b2u(h1)) : "memory");
                asm volatile("st.shared.v2.b32 [%0], {%1,%2};"
                             :: "r"(sb + OFF_XL + off), "r"(b2u(L0)), "r"(b2u(L1)) : "memory");
            }
        }
        __syncthreads();

        // ---- accumulators: [mat(log/ang)][mtile][ntile][4] ----
        float acc[2][2][8][4];
        #pragma unroll
        for (int m = 0; m < 2; ++m)
            #pragma unroll
            for (int i = 0; i < 2; ++i)
                #pragma unroll
                for (int n = 0; n < 8; ++n)
                    #pragma unroll
                    for (int q = 0; q < 4; ++q) acc[m][i][n][q] = 0.f;

        // ---- fused k-loop: every fragment loaded once per k-step ----
        uint32_t ah[2][2][4], al[2][2][4];   // [buf][mi][4]
        ldsm_x4(ah[0][0], abase_h);
        ldsm_x4(ah[0][1], abase_h + MI_STEP);
        ldsm_x4(al[0][0], abase_l);
        ldsm_x4(al[0][1], abase_l + MI_STEP);

        #pragma unroll
        for (int k = 0; k < 8; ++k) {
            const int cur = k & 1, nxt = cur ^ 1;
            const uint32_t kb = (uint32_t)k * 32u;

            // prefetch next k's A fragments
            if (k < 7) {
                const uint32_t kn = kb + 32u;
                ldsm_x4(ah[nxt][0], abase_h + kn);
                ldsm_x4(ah[nxt][1], abase_h + MI_STEP + kn);
                ldsm_x4(al[nxt][0], abase_l + kn);
                ldsm_x4(al[nxt][1], abase_l + MI_STEP + kn);
            }

            // ---- group 1: hi-weights (logH=mat0 -> acc[0], angH=mat2 -> acc[1]) ----
            {
                uint32_t b[2][4][4];
                #pragma unroll
                for (int s = 0; s < 2; ++s) {
                    const uint32_t wb = sb + OFF_W + (uint32_t)(s * 2) * 34816u + boff + kb;
                    #pragma unroll
                    for (int np = 0; np < 4; ++np)
                        ldsm_x4(b[s][np], wb + (uint32_t)np * MI_STEP);
                }
                // all xh-HMMAs first, then all xl-HMMAs (spaces acc RAW pairs)
                #pragma unroll
                for (int s = 0; s < 2; ++s)
                    #pragma unroll
                    for (int np = 0; np < 4; ++np) {
                        mma16816(acc[s][0][np * 2],     ah[cur][0], b[s][np][0], b[s][np][1]);
                        mma16816(acc[s][1][np * 2],     ah[cur][1], b[s][np][0], b[s][np][1]);
                        mma16816(acc[s][0][np * 2 + 1], ah[cur][0], b[s][np][2], b[s][np][3]);
                        mma16816(acc[s][1][np * 2 + 1], ah[cur][1], b[s][np][2], b[s][np][3]);
                    }
                #pragma unroll
                for (int s = 0; s < 2; ++s)
                    #pragma unroll
                    for (int np = 0; np < 4; ++np) {
                        mma16816(acc[s][0][np * 2],     al[cur][0], b[s][np][0], b[s][np][1]);
                        mma16816(acc[s][1][np * 2],     al[cur][1], b[s][np][0], b[s][np][1]);
                        mma16816(acc[s][0][np * 2 + 1], al[cur][0], b[s][np][2], b[s][np][3]);
                        mma16816(acc[s][1][np * 2 + 1], al[cur][1], b[s][np][2], b[s][np][3]);
                    }
            }

            // ---- group 2: lo-weights (logL=mat1 -> acc[0], angL=mat3 -> acc[1]), xh only ----
            {
                uint32_t b[2][4][4];
                #pragma unroll
                for (int s = 0; s < 2; ++s) {
                    const uint32_t wb = sb + OFF_W + (uint32_t)(s * 2 + 1) * 34816u + boff + kb;
                    #pragma unroll
                    for (int np = 0; np < 4; ++np)
                        ldsm_x4(b[s][np], wb + (uint32_t)np * MI_STEP);
                }
                #pragma unroll
                for (int s = 0; s < 2; ++s)
                    #pragma unroll
                    for (int np = 0; np < 4; ++np) {
                        mma16816(acc[s][0][np * 2],     ah[cur][0], b[s][np][0], b[s][np][1]);
                        mma16816(acc[s][1][np * 2],     ah[cur][1], b[s][np][0], b[s][np][1]);
                        mma16816(acc[s][0][np * 2 + 1], ah[cur][0], b[s][np][2], b[s][np][3]);
                        mma16816(acc[s][1][np * 2 + 1], ah[cur][1], b[s][np][2], b[s][np][3]);
                    }
            }
        }

        // ---- epilogue: out = cos(ang + bias) * exp(log) ----
        #pragma unroll
        for (int mt = 0; mt < 2; ++mt) {
            size_t r0 = (size_t)tile * 128 + wm * 32 + mt * 16 + (lane >> 2);
            float* p0 = out + r0 * 128 + wn * 64 + 2 * (lane & 3);
            #pragma unroll
            for (int nt = 0; nt < 8; ++nt) {
                const float* al_ = acc[1][mt][nt];
                const float* lg  = acc[0][mt][nt];
                float2 o0, o1;
                o0.x = __cosf(al_[0] + bs0[nt]) * __expf(lg[0]);
                o0.y = __cosf(al_[1] + bs1[nt]) * __expf(lg[1]);
                o1.x = __cosf(al_[2] + bs0[nt]) * __expf(lg[2]);
                o1.y = __cosf(al_[3] + bs1[nt]) * __expf(lg[3]);
                *(float2*)(p0 + nt * 8) = o0;
                *(float2*)(p0 + nt * 8 + 8 * 128) = o1;
            }
        }
    }
}

// ---------------------------------------------------------------------------
extern "C" void kernel_launch(void* const* d_in, const int* in_sizes, int n_in,
                              void* d_out, int out_size) {
    const float* x    = (const float*)d_in[0];
    const float* wr   = (const float*)d_in[1];
    const float* wi   = (const float*)d_in[2];
    const float* bias = (const float*)d_in[3];
    float* out = (float*)d_out;
    (void)in_sizes; (void)n_in; (void)out_size;

    cudaFuncSetAttribute(ces_main, cudaFuncAttributeMaxDynamicSharedMemorySize,
                         (int)SMEM_BYTES);

    ces_prep<<<64, 256>>>(wr, wi);
    ces_main<<<148, 256, SMEM_BYTES>>>(x, bias, out);
}

// round 4
// speedup vs baseline: 1.3164x; 1.0509x over previous
#include <cuda_runtime.h>
#include <cuda_bf16.h>
#include <cstdint>

// ============================================================================
// CESLayer: out[b,o] = cos( x@angle^T + bias ) * exp( x@log|w|^T )
// B=262144, I=O=128.  mma.sync bf16 with hi/lo split (xh*Wh + xl*Wh + xh*Wl).
// R4: CTA split into 2 independent 4-warp groups on different 64-row tiles
//     (phase overlap: one group's load/epilogue hides under the other's MMA).
// ============================================================================

#define N_TILES   4096            // 64-row tiles
#define LDS_STRIDE 136            // bf16 elems per smem row (128+8 pad)

// smem byte offsets
// group g X: [g*34816, g*34816+17408) hi, +17408 lo   (64 rows x 136 x bf16)
#define OFF_W    69632u           // 4 mats * 34816: [logH, logL, angH, angL]
#define OFF_BIAS 208896u
#define SMEM_BYTES 209664u

__device__ __align__(16) __nv_bfloat16 g_W[4 * 16384];

// ---------------------------------------------------------------------------
__device__ __forceinline__ uint32_t smem_u32(const void* p) {
    uint32_t a;
    asm("{ .reg .u64 t; cvta.to.shared.u64 t, %1; cvt.u32.u64 %0, t; }"
        : "=r"(a) : "l"(p));
    return a;
}

__device__ __forceinline__ uint32_t b2u(__nv_bfloat162 v) {
    return *reinterpret_cast<uint32_t*>(&v);
}

__device__ __forceinline__ void ldsm_x4(uint32_t r[4], uint32_t addr) {
    asm volatile("ldmatrix.sync.aligned.m8n8.x4.shared.b16 {%0,%1,%2,%3}, [%4];"
                 : "=r"(r[0]), "=r"(r[1]), "=r"(r[2]), "=r"(r[3]) : "r"(addr));
}

__device__ __forceinline__ void mma16816(float c[4], const uint32_t a[4],
                                         uint32_t b0, uint32_t b1) {
    asm volatile(
        "mma.sync.aligned.m16n8k16.row.col.f32.bf16.bf16.f32 "
        "{%0,%1,%2,%3}, {%4,%5,%6,%7}, {%8,%9}, {%0,%1,%2,%3};"
        : "+f"(c[0]), "+f"(c[1]), "+f"(c[2]), "+f"(c[3])
        : "r"(a[0]), "r"(a[1]), "r"(a[2]), "r"(a[3]), "r"(b0), "r"(b1));
}

#define GBAR(id) asm volatile("bar.sync %0, 128;" :: "r"(id) : "memory")

// ---------------------------------------------------------------------------
__global__ void ces_prep(const float* __restrict__ wr, const float* __restrict__ wi) {
    int idx = blockIdx.x * blockDim.x + threadIdx.x;
    if (idx >= 16384) return;
    float a = wr[idx], b = wi[idx];
    float la = 0.5f * logf(fmaf(a, a, b * b));
    float an = atan2f(b, a);
    __nv_bfloat16 lah = __float2bfloat16(la);
    __nv_bfloat16 lal = __float2bfloat16(la - __bfloat162float(lah));
    __nv_bfloat16 anh = __float2bfloat16(an);
    __nv_bfloat16 anl = __float2bfloat16(an - __bfloat162float(anh));
    g_W[0 * 16384 + idx] = lah;
    g_W[1 * 16384 + idx] = lal;
    g_W[2 * 16384 + idx] = anh;
    g_W[3 * 16384 + idx] = anl;
}

// ---------------------------------------------------------------------------
// 8 warps = 2 groups x 4 warps. Group tile: 64 rows x 128 cols.
// Within group: wm = lwid&1 (32 rows), wn = lwid>>1 (64 cols).
// ---------------------------------------------------------------------------
__global__ void __launch_bounds__(256, 1)
ces_main(const float* __restrict__ x, const float* __restrict__ bias,
         float* __restrict__ out) {
    extern __shared__ char smem[];
    const uint32_t sb = smem_u32(smem);
    const int tid  = threadIdx.x;
    const int lane = tid & 31;
    const int wid  = tid >> 5;
    const int g    = wid >> 2;        // group 0/1
    const int lwid = wid & 3;         // warp in group
    const int wm   = lwid & 1;
    const int wn   = lwid >> 1;

    // ---- copy W into padded smem, once (all 256 threads) ----
    for (int r = tid; r < 512; r += 256) {
        const uint4* src = (const uint4*)(g_W + r * 128);
        uint4* dst = (uint4*)(smem + OFF_W + ((uint32_t)(r >> 7) * 17408u +
                                              (uint32_t)(r & 127) * LDS_STRIDE) * 2u);
        #pragma unroll
        for (int j = 0; j < 16; ++j) dst[j] = src[j];
    }
    if (tid < 128) ((float*)(smem + OFF_BIAS))[tid] = bias[tid];
    __syncthreads();

    // per-thread bias pairs (tile-invariant)
    float bs0[8], bs1[8];
    {
        const float* sbias = (const float*)(smem + OFF_BIAS);
        #pragma unroll
        for (int nt = 0; nt < 8; ++nt) {
            int c = wn * 64 + nt * 8 + 2 * (lane & 3);
            bs0[nt] = sbias[c];
            bs1[nt] = sbias[c + 1];
        }
    }

    // ldmatrix per-thread byte offsets
    const uint32_t aoff = ((uint32_t)(wm * 32 + (lane & 15)) * LDS_STRIDE +
                           (uint32_t)((lane >> 4) * 8)) * 2u;
    const uint32_t boff = ((uint32_t)(wn * 64 + ((lane & 7) | ((lane & 16) >> 1))) * LDS_STRIDE +
                           (uint32_t)(lane & 8)) * 2u;

    const uint32_t xbase   = sb + (uint32_t)g * 34816u;
    const uint32_t abase_h = xbase + aoff;
    const uint32_t abase_l = xbase + 17408u + aoff;
    const uint32_t MI_STEP = 16u * LDS_STRIDE * 2u;

    const int xrow0 = lwid;           // rows lwid + 4*j  (64 rows, 128 threads)
    const int xcol  = lane * 4;
    const int bar_id = g + 1;

    for (int tile = blockIdx.x * 2 + g; tile < N_TILES; tile += 2 * gridDim.x) {
        GBAR(bar_id);   // group's previous-tile ldsm done before X rewrite

        // ---- load x (coalesced), split hi/lo, STS ----
        #pragma unroll
        for (int jb = 0; jb < 2; ++jb) {
            float4 v[8];
            #pragma unroll
            for (int j = 0; j < 8; ++j) {
                size_t row = (size_t)tile * 64 + xrow0 + 4 * (jb * 8 + j);
                v[j] = __ldg((const float4*)(x + row * 128 + xcol));
            }
            #pragma unroll
            for (int j = 0; j < 8; ++j) {
                int row = xrow0 + 4 * (jb * 8 + j);
                __nv_bfloat162 h0 = __float22bfloat162_rn(make_float2(v[j].x, v[j].y));
                __nv_bfloat162 h1 = __float22bfloat162_rn(make_float2(v[j].z, v[j].w));
                __nv_bfloat162 L0 = __float22bfloat162_rn(make_float2(
                    v[j].x - __bfloat162float(h0.x), v[j].y - __bfloat162float(h0.y)));
                __nv_bfloat162 L1 = __float22bfloat162_rn(make_float2(
                    v[j].z - __bfloat162float(h1.x), v[j].w - __bfloat162float(h1.y)));
                uint32_t off = ((uint32_t)row * LDS_STRIDE + (uint32_t)xcol) * 2u;
                asm volatile("st.shared.v2.b32 [%0], {%1,%2};"
                             :: "r"(xbase + off), "r"(b2u(h0)), "r"(b2u(h1)) : "memory");
                asm volatile("st.shared.v2.b32 [%0], {%1,%2};"
                             :: "r"(xbase + 17408u + off), "r"(b2u(L0)), "r"(b2u(L1)) : "memory");
            }
        }
        GBAR(bar_id);

        // ---- accumulators: [mat(log/ang)][mtile][ntile][4] ----
        float acc[2][2][8][4];
        #pragma unroll
        for (int m = 0; m < 2; ++m)
            #pragma unroll
            for (int i = 0; i < 2; ++i)
                #pragma unroll
                for (int n = 0; n < 8; ++n)
                    #pragma unroll
                    for (int q = 0; q < 4; ++q) acc[m][i][n][q] = 0.f;

        // ---- fused k-loop: every fragment loaded once per k-step ----
        uint32_t ah[2][2][4], al[2][2][4];   // [buf][mi][4]
        ldsm_x4(ah[0][0], abase_h);
        ldsm_x4(ah[0][1], abase_h + MI_STEP);
        ldsm_x4(al[0][0], abase_l);
        ldsm_x4(al[0][1], abase_l + MI_STEP);

        #pragma unroll
        for (int k = 0; k < 8; ++k) {
            const int cur = k & 1, nxt = cur ^ 1;
            const uint32_t kb = (uint32_t)k * 32u;

            if (k < 7) {
                const uint32_t kn = kb + 32u;
                ldsm_x4(ah[nxt][0], abase_h + kn);
                ldsm_x4(ah[nxt][1], abase_h + MI_STEP + kn);
                ldsm_x4(al[nxt][0], abase_l + kn);
                ldsm_x4(al[nxt][1], abase_l + MI_STEP + kn);
            }

            // ---- group 1: hi-weights (logH, angH), xh then xl ----
            {
                uint32_t b[2][4][4];
                #pragma unroll
                for (int s = 0; s < 2; ++s) {
                    const uint32_t wb = sb + OFF_W + (uint32_t)(s * 2) * 34816u + boff + kb;
                    #pragma unroll
                    for (int np = 0; np < 4; ++np)
                        ldsm_x4(b[s][np], wb + (uint32_t)np * MI_STEP);
                }
                #pragma unroll
                for (int s = 0; s < 2; ++s)
                    #pragma unroll
                    for (int np = 0; np < 4; ++np) {
                        mma16816(acc[s][0][np * 2],     ah[cur][0], b[s][np][0], b[s][np][1]);
                        mma16816(acc[s][1][np * 2],     ah[cur][1], b[s][np][0], b[s][np][1]);
                        mma16816(acc[s][0][np * 2 + 1], ah[cur][0], b[s][np][2], b[s][np][3]);
                        mma16816(acc[s][1][np * 2 + 1], ah[cur][1], b[s][np][2], b[s][np][3]);
                    }
                #pragma unroll
                for (int s = 0; s < 2; ++s)
                    #pragma unroll
                    for (int np = 0; np < 4; ++np) {
                        mma16816(acc[s][0][np * 2],     al[cur][0], b[s][np][0], b[s][np][1]);
                        mma16816(acc[s][1][np * 2],     al[cur][1], b[s][np][0], b[s][np][1]);
                        mma16816(acc[s][0][np * 2 + 1], al[cur][0], b[s][np][2], b[s][np][3]);
                        mma16816(acc[s][1][np * 2 + 1], al[cur][1], b[s][np][2], b[s][np][3]);
                    }
            }

            // ---- group 2: lo-weights (logL, angL), xh only ----
            {
                uint32_t b[2][4][4];
                #pragma unroll
                for (int s = 0; s < 2; ++s) {
                    const uint32_t wb = sb + OFF_W + (uint32_t)(s * 2 + 1) * 34816u + boff + kb;
                    #pragma unroll
                    for (int np = 0; np < 4; ++np)
                        ldsm_x4(b[s][np], wb + (uint32_t)np * MI_STEP);
                }
                #pragma unroll
                for (int s = 0; s < 2; ++s)
                    #pragma unroll
                    for (int np = 0; np < 4; ++np) {
                        mma16816(acc[s][0][np * 2],     ah[cur][0], b[s][np][0], b[s][np][1]);
                        mma16816(acc[s][1][np * 2],     ah[cur][1], b[s][np][0], b[s][np][1]);
                        mma16816(acc[s][0][np * 2 + 1], ah[cur][0], b[s][np][2], b[s][np][3]);
                        mma16816(acc[s][1][np * 2 + 1], ah[cur][1], b[s][np][2], b[s][np][3]);
                    }
            }
        }

        // ---- epilogue: out = cos(ang + bias) * exp(log) ----
        #pragma unroll
        for (int mt = 0; mt < 2; ++mt) {
            size_t r0 = (size_t)tile * 64 + wm * 32 + mt * 16 + (lane >> 2);
            float* p0 = out + r0 * 128 + wn * 64 + 2 * (lane & 3);
            #pragma unroll
            for (int nt = 0; nt < 8; ++nt) {
                const float* al_ = acc[1][mt][nt];
                const float* lg  = acc[0][mt][nt];
                float2 o0, o1;
                o0.x = __cosf(al_[0] + bs0[nt]) * __expf(lg[0]);
                o0.y = __cosf(al_[1] + bs1[nt]) * __expf(lg[1]);
                o1.x = __cosf(al_[2] + bs0[nt]) * __expf(lg[2]);
                o1.y = __cosf(al_[3] + bs1[nt]) * __expf(lg[3]);
                *(float2*)(p0 + nt * 8) = o0;
                *(float2*)(p0 + nt * 8 + 8 * 128) = o1;
            }
        }
    }
}

// ---------------------------------------------------------------------------
extern "C" void kernel_launch(void* const* d_in, const int* in_sizes, int n_in,
                              void* d_out, int out_size) {
    const float* x    = (const float*)d_in[0];
    const float* wr   = (const float*)d_in[1];
    const float* wi   = (const float*)d_in[2];
    const float* bias = (const float*)d_in[3];
    float* out = (float*)d_out;
    (void)in_sizes; (void)n_in; (void)out_size;

    cudaFuncSetAttribute(ces_main, cudaFuncAttributeMaxDynamicSharedMemorySize,
                         (int)SMEM_BYTES);

    ces_prep<<<64, 256>>>(wr, wi);
    ces_main<<<148, 256, SMEM_BYTES>>>(x, bias, out);
}